// round 7
// baseline (speedup 1.0000x reference)
#include <cuda_runtime.h>
#include <cuda_fp16.h>
#include <math.h>
#include <stdint.h>

#define DIM   1024
#define BATCH 2
#define SEQ   2048
#define NHEAD 16
#define HDIM  64
#define NTOK  (BATCH * SEQ)
#define HID   (4 * DIM)
#define QKVS  (3 * DIM)
#define ATTN_SCALE 0.125f
#define LN_EPS 1e-5f
#define LSCALE 2048.0f
#define CSCALE (1.0f / 2048.0f)

// ===========================================================================
// PTX helpers
// ===========================================================================
static __device__ __forceinline__ uint32_t smem_u32(const void* p) {
    uint32_t a;
    asm("{ .reg .u64 t; cvta.to.shared.u64 t, %1; cvt.u32.u64 %0, t; }"
        : "=r"(a) : "l"(p));
    return a;
}

#define LDSM4(r0, r1, r2, r3, addr) \
    asm volatile("ldmatrix.sync.aligned.m8n8.x4.shared.b16 {%0,%1,%2,%3}, [%4];" \
        : "=r"(r0), "=r"(r1), "=r"(r2), "=r"(r3) : "r"(addr))

#define LDSM4T(r0, r1, r2, r3, addr) \
    asm volatile("ldmatrix.sync.aligned.m8n8.x4.trans.shared.b16 {%0,%1,%2,%3}, [%4];" \
        : "=r"(r0), "=r"(r1), "=r"(r2), "=r"(r3) : "r"(addr))

// fp16 operands, fp32 accumulate
#define MMAF(d, a0, a1, a2, a3, b0, b1) \
    asm volatile("mma.sync.aligned.m16n8k16.row.col.f32.f16.f16.f32 " \
        "{%0,%1,%2,%3}, {%4,%5,%6,%7}, {%8,%9}, {%0,%1,%2,%3};" \
        : "+f"((d)[0]), "+f"((d)[1]), "+f"((d)[2]), "+f"((d)[3]) \
        : "r"(a0), "r"(a1), "r"(a2), "r"(a3), "r"(b0), "r"(b1))

// fp16 operands, fp16 accumulate (double-rate correction path)
#define MMAC(d, a0, a1, a2, a3, b0, b1) \
    asm volatile("mma.sync.aligned.m16n8k16.row.col.f16.f16.f16.f16 " \
        "{%0,%1}, {%2,%3,%4,%5}, {%6,%7}, {%0,%1};" \
        : "+r"((d)[0]), "+r"((d)[1]) \
        : "r"(a0), "r"(a1), "r"(a2), "r"(a3), "r"(b0), "r"(b1))

#define CPA16(dst, src) \
    asm volatile("cp.async.cg.shared.global [%0], [%1], 16;" :: "r"(dst), "l"(src))
#define CPA4(dst, src) \
    asm volatile("cp.async.ca.shared.global [%0], [%1], 4;" :: "r"(dst), "l"(src))
#define CP_COMMIT() asm volatile("cp.async.commit_group;")
template<int N> static __device__ __forceinline__ void cp_wait() {
    asm volatile("cp.async.wait_group %0;" :: "n"(N));
}

static __device__ __forceinline__ uint32_t pack_h2(float a, float b) {
    __half2 t = __floats2half2_rn(a, b);
    return *reinterpret_cast<uint32_t*>(&t);
}
static __device__ __forceinline__ float2 unpack_h2(uint32_t u) {
    __half2 t = *reinterpret_cast<__half2*>(&u);
    return __half22float2(t);
}

// ===========================================================================
// Scratch
// ===========================================================================
__device__ float g_x1 [NTOK * DIM];

__device__ __half g_nx_hi [NTOK * DIM],  g_nx_lo [NTOK * DIM];
__device__ __half g_qkv_hi[NTOK * QKVS], g_qkv_lo[NTOK * QKVS];
__device__ __half g_at_hi [NTOK * DIM],  g_at_lo [NTOK * DIM];
__device__ __half g_h_hi  [NTOK * HID],  g_h_lo  [NTOK * HID];
__device__ __half g_wqkv_hi[QKVS * DIM], g_wqkv_lo[QKVS * DIM];
__device__ __half g_wo_hi [DIM * DIM],   g_wo_lo [DIM * DIM];
__device__ __half g_m1_hi [HID * DIM],   g_m1_lo [HID * DIM];
__device__ __half g_m2_hi [DIM * HID],   g_m2_lo [DIM * HID];

// ===========================================================================
// fused fp32 -> fp16 hi/lo weight splits (lo scaled by 2048)
// ===========================================================================
static __device__ __forceinline__ void split4(
    const float* __restrict__ src, __half* __restrict__ hi,
    __half* __restrict__ lo, int i)
{
    float4 v = *reinterpret_cast<const float4*>(src + i);
    __half2 h01 = __floats2half2_rn(v.x, v.y);
    __half2 h23 = __floats2half2_rn(v.z, v.w);
    __half2 l01 = __floats2half2_rn((v.x - __low2float(h01)) * LSCALE,
                                    (v.y - __high2float(h01)) * LSCALE);
    __half2 l23 = __floats2half2_rn((v.z - __low2float(h23)) * LSCALE,
                                    (v.w - __high2float(h23)) * LSCALE);
    *reinterpret_cast<__half2*>(hi + i)     = h01;
    *reinterpret_cast<__half2*>(hi + i + 2) = h23;
    *reinterpret_cast<__half2*>(lo + i)     = l01;
    *reinterpret_cast<__half2*>(lo + i + 2) = l23;
}

// attention weights: wq,wk,wv (into fused qkv layout), wo.  4096 blocks.
__global__ __launch_bounds__(256) void split_attn_w(
    const float* __restrict__ wq, const float* __restrict__ wk,
    const float* __restrict__ wv, const float* __restrict__ wo,
    __half* __restrict__ qkvh, __half* __restrict__ qkvl,
    __half* __restrict__ woh, __half* __restrict__ wol)
{
    int sel = blockIdx.x >> 10;
    int i = ((blockIdx.x & 1023) * 256 + threadIdx.x) * 4;
    if      (sel == 0) split4(wq, qkvh,                 qkvl,                 i);
    else if (sel == 1) split4(wk, qkvh + DIM * DIM,     qkvl + DIM * DIM,     i);
    else if (sel == 2) split4(wv, qkvh + 2 * DIM * DIM, qkvl + 2 * DIM * DIM, i);
    else               split4(wo, woh, wol, i);
}

// mlp weights: m1 (4M), m2 (4M).  8192 blocks.
__global__ __launch_bounds__(256) void split_mlp_w(
    const float* __restrict__ m1, const float* __restrict__ m2,
    __half* __restrict__ m1h, __half* __restrict__ m1l,
    __half* __restrict__ m2h, __half* __restrict__ m2l)
{
    int sel = blockIdx.x >> 12;
    int i = ((blockIdx.x & 4095) * 256 + threadIdx.x) * 4;
    if (sel == 0) split4(m1, m1h, m1l, i);
    else          split4(m2, m2h, m2l, i);
}

// ===========================================================================
// LayerNorm -> fp16 hi/lo
// ===========================================================================
__global__ __launch_bounds__(256) void ln_hilo_kernel(
    const float* __restrict__ x, const float* __restrict__ g,
    const float* __restrict__ b, __half* __restrict__ yh,
    __half* __restrict__ yl)
{
    int row = blockIdx.x;
    int tid = threadIdx.x;
    const float4* xr = reinterpret_cast<const float4*>(x + (size_t)row * DIM);
    float4 v = xr[tid];
    float s  = v.x + v.y + v.z + v.w;
    float sq = v.x*v.x + v.y*v.y + v.z*v.z + v.w*v.w;
    #pragma unroll
    for (int o = 16; o > 0; o >>= 1) {
        s  += __shfl_xor_sync(0xffffffffu, s,  o);
        sq += __shfl_xor_sync(0xffffffffu, sq, o);
    }
    __shared__ float rs[8], rq[8];
    int warp = tid >> 5, lane = tid & 31;
    if (lane == 0) { rs[warp] = s; rq[warp] = sq; }
    __syncthreads();
    if (warp == 0) {
        float a = (lane < 8) ? rs[lane] : 0.f;
        float c = (lane < 8) ? rq[lane] : 0.f;
        #pragma unroll
        for (int o = 4; o > 0; o >>= 1) {
            a += __shfl_xor_sync(0xffffffffu, a, o);
            c += __shfl_xor_sync(0xffffffffu, c, o);
        }
        if (lane == 0) { rs[0] = a; rq[0] = c; }
    }
    __syncthreads();
    float mean = rs[0] * (1.0f / DIM);
    float var  = rq[0] * (1.0f / DIM) - mean * mean;
    float inv  = rsqrtf(var + LN_EPS);
    float4 gv = reinterpret_cast<const float4*>(g)[tid];
    float4 bv = reinterpret_cast<const float4*>(b)[tid];
    float o0 = (v.x - mean) * inv * gv.x + bv.x;
    float o1 = (v.y - mean) * inv * gv.y + bv.y;
    float o2 = (v.z - mean) * inv * gv.z + bv.z;
    float o3 = (v.w - mean) * inv * gv.w + bv.w;
    size_t base = (size_t)row * DIM + tid * 4;
    __half2 h01 = __floats2half2_rn(o0, o1);
    __half2 h23 = __floats2half2_rn(o2, o3);
    __half2 l01 = __floats2half2_rn((o0 - __low2float(h01)) * LSCALE,
                                    (o1 - __high2float(h01)) * LSCALE);
    __half2 l23 = __floats2half2_rn((o2 - __low2float(h23)) * LSCALE,
                                    (o3 - __high2float(h23)) * LSCALE);
    *reinterpret_cast<__half2*>(yh + base)     = h01;
    *reinterpret_cast<__half2*>(yh + base + 2) = h23;
    *reinterpret_cast<__half2*>(yl + base)     = l01;
    *reinterpret_cast<__half2*>(yl + base + 2) = l23;
}

// ===========================================================================
// fp16 HMMA GEMM: main term fp32-accum, corrections fp16-accum (2x rate).
// CTA tile 128x64, BK=32, 8 warps (warp tile 32x32), double buffer, occ 2.
// ===========================================================================
#define EPI_RESID      1
#define EPI_BIAS_RESID 3
#define EPI_HILO       4
#define EPI_GELU_HILO  5

__device__ __forceinline__ float gelu_exact(float x) {
    return 0.5f * x * (1.0f + erff(x * 0.70710678118654752f));
}

#define ROWB      80
#define PLANE_A   (128 * ROWB)         // 10240
#define PLANE_B   (64 * ROWB)          // 5120
#define OFF_AHI   0
#define OFF_ALO   (PLANE_A)
#define OFF_BHI   (2 * PLANE_A)
#define OFF_BLO   (2 * PLANE_A + PLANE_B)
#define BUF_SZ    (2 * PLANE_A + 2 * PLANE_B)   // 30720
#define GEMM_SMEM (2 * BUF_SZ)                  // 61440

template<int EPI>
__global__ __launch_bounds__(256, 2) void gemm_tc(
    const __half* __restrict__ Ahi, const __half* __restrict__ Alo,
    const __half* __restrict__ Whi, const __half* __restrict__ Wlo,
    const float* __restrict__ bias, const float* __restrict__ resid,
    float* __restrict__ Y, __half* __restrict__ Yh,
    __half* __restrict__ Yl, int M, int N, int K)
{
    extern __shared__ char smem[];
    const uint32_t sb = smem_u32(smem);
    const int tid  = threadIdx.x;
    const int lane = tid & 31;
    const int wid  = tid >> 5;
    const int bm = blockIdx.y * 128;
    const int bn = blockIdx.x * 64;
    const int wm = (wid & 3) * 32;
    const int wn = (wid >> 2) * 32;

    float acc[2][4][4];
    uint32_t corr[2][4][2];
    #pragma unroll
    for (int i = 0; i < 2; i++)
        #pragma unroll
        for (int j = 0; j < 4; j++) {
            #pragma unroll
            for (int t = 0; t < 4; t++) acc[i][j][t] = 0.f;
            corr[i][j][0] = 0u; corr[i][j][1] = 0u;
        }

    const int a0r = tid >> 2,         a0c = tid & 3;
    const int a1r = (tid + 256) >> 2;
    const int b0r = tid >> 2,         b0c = tid & 3;

    const uint32_t a_row   = wm + (lane & 15);
    const uint32_t a_cbyte = (lane >> 4) * 16;
    const uint32_t b_row0  = wn + ((lane >> 4) & 1) * 8 + (lane & 7);
    const uint32_t b_cbyte = ((lane >> 3) & 1) * 16;

    const int NC = K >> 5;

#define LOAD_CHUNK(cidx, bufbase)                                              \
    do {                                                                       \
        const int _k0 = (cidx) << 5;                                           \
        {                                                                      \
            size_t s0 = (size_t)(bm + a0r) * K + _k0 + a0c * 8;                \
            size_t s1 = (size_t)(bm + a1r) * K + _k0 + a0c * 8;                \
            uint32_t d0 = (bufbase) + a0r * ROWB + a0c * 16;                   \
            uint32_t d1 = (bufbase) + a1r * ROWB + a0c * 16;                   \
            CPA16(d0 + OFF_AHI, Ahi + s0); CPA16(d1 + OFF_AHI, Ahi + s1);      \
            CPA16(d0 + OFF_ALO, Alo + s0); CPA16(d1 + OFF_ALO, Alo + s1);      \
        }                                                                      \
        {                                                                      \
            size_t s0 = (size_t)(bn + b0r) * K + _k0 + b0c * 8;                \
            uint32_t d0 = (bufbase) + b0r * ROWB + b0c * 16;                   \
            CPA16(d0 + OFF_BHI, Whi + s0);                                     \
            CPA16(d0 + OFF_BLO, Wlo + s0);                                     \
        }                                                                      \
    } while (0)

    LOAD_CHUNK(0, sb);
    CP_COMMIT();

    for (int c = 0; c < NC; c++) {
        const uint32_t buf = sb + (uint32_t)(c & 1) * BUF_SZ;
        if (c + 1 < NC) {
            LOAD_CHUNK(c + 1, sb + (uint32_t)((c + 1) & 1) * BUF_SZ);
            CP_COMMIT();
            cp_wait<1>();
        } else {
            cp_wait<0>();
        }
        __syncthreads();

        #pragma unroll
        for (int k16 = 0; k16 < 2; k16++) {
            const uint32_t kb = k16 * 32;
            uint32_t ah[2][4], al[2][4];
            #pragma unroll
            for (int mi = 0; mi < 2; mi++) {
                uint32_t ad = buf + (a_row + mi * 16) * ROWB + kb + a_cbyte;
                LDSM4(ah[mi][0], ah[mi][1], ah[mi][2], ah[mi][3], ad + OFF_AHI);
                LDSM4(al[mi][0], al[mi][1], al[mi][2], al[mi][3], ad + OFF_ALO);
            }
            #pragma unroll
            for (int p = 0; p < 2; p++) {
                uint32_t bh4[4], bl4[4];
                uint32_t bd = buf + (b_row0 + p * 16) * ROWB + kb + b_cbyte;
                LDSM4(bh4[0], bh4[1], bh4[2], bh4[3], bd + OFF_BHI);
                LDSM4(bl4[0], bl4[1], bl4[2], bl4[3], bd + (OFF_BLO - OFF_BHI) + OFF_BHI + PLANE_B - PLANE_B);
                LDSM4(bl4[0], bl4[1], bl4[2], bl4[3], bd + OFF_BLO);
                #pragma unroll
                for (int mi = 0; mi < 2; mi++) {
                    #pragma unroll
                    for (int jj = 0; jj < 2; jj++) {
                        const int j = p * 2 + jj, q = jj * 2;
                        MMAF(acc[mi][j], ah[mi][0], ah[mi][1], ah[mi][2], ah[mi][3],
                             bh4[q], bh4[q + 1]);
                        MMAC(corr[mi][j], ah[mi][0], ah[mi][1], ah[mi][2], ah[mi][3],
                             bl4[q], bl4[q + 1]);
                        MMAC(corr[mi][j], al[mi][0], al[mi][1], al[mi][2], al[mi][3],
                             bh4[q], bh4[q + 1]);
                    }
                }
            }
        }
        __syncthreads();
    }
#undef LOAD_CHUNK

    #pragma unroll
    for (int mi = 0; mi < 2; mi++) {
        const int r0 = bm + wm + mi * 16 + (lane >> 2);
        #pragma unroll
        for (int j = 0; j < 4; j++) {
            const int col = bn + wn + j * 8 + (lane & 3) * 2;
            float2 c01 = unpack_h2(corr[mi][j][0]);
            float2 c23 = unpack_h2(corr[mi][j][1]);
            float2 v0 = make_float2(acc[mi][j][0] + c01.x * CSCALE,
                                    acc[mi][j][1] + c01.y * CSCALE);
            float2 v1 = make_float2(acc[mi][j][2] + c23.x * CSCALE,
                                    acc[mi][j][3] + c23.y * CSCALE);
            if (EPI == EPI_GELU_HILO) {
                float2 bb = *reinterpret_cast<const float2*>(bias + col);
                v0.x = gelu_exact(v0.x + bb.x);  v0.y = gelu_exact(v0.y + bb.y);
                v1.x = gelu_exact(v1.x + bb.x);  v1.y = gelu_exact(v1.y + bb.y);
            } else if (EPI == EPI_BIAS_RESID) {
                float2 bb = *reinterpret_cast<const float2*>(bias + col);
                float2 r0v = *reinterpret_cast<const float2*>(resid + (size_t)r0 * N + col);
                float2 r1v = *reinterpret_cast<const float2*>(resid + (size_t)(r0 + 8) * N + col);
                v0.x += bb.x + r0v.x;  v0.y += bb.y + r0v.y;
                v1.x += bb.x + r1v.x;  v1.y += bb.y + r1v.y;
            } else if (EPI == EPI_RESID) {
                float2 r0v = *reinterpret_cast<const float2*>(resid + (size_t)r0 * N + col);
                float2 r1v = *reinterpret_cast<const float2*>(resid + (size_t)(r0 + 8) * N + col);
                v0.x += r0v.x;  v0.y += r0v.y;
                v1.x += r1v.x;  v1.y += r1v.y;
            }
            if (EPI == EPI_HILO || EPI == EPI_GELU_HILO) {
                __half2 h0 = __floats2half2_rn(v0.x, v0.y);
                __half2 h1 = __floats2half2_rn(v1.x, v1.y);
                __half2 l0 = __floats2half2_rn((v0.x - __low2float(h0)) * LSCALE,
                                               (v0.y - __high2float(h0)) * LSCALE);
                __half2 l1 = __floats2half2_rn((v1.x - __low2float(h1)) * LSCALE,
                                               (v1.y - __high2float(h1)) * LSCALE);
                *reinterpret_cast<__half2*>(Yh + (size_t)r0 * N + col)       = h0;
                *reinterpret_cast<__half2*>(Yh + (size_t)(r0 + 8) * N + col) = h1;
                *reinterpret_cast<__half2*>(Yl + (size_t)r0 * N + col)       = l0;
                *reinterpret_cast<__half2*>(Yl + (size_t)(r0 + 8) * N + col) = l1;
            } else {
                *reinterpret_cast<float2*>(Y + (size_t)r0 * N + col)       = v0;
                *reinterpret_cast<float2*>(Y + (size_t)(r0 + 8) * N + col) = v1;
            }
        }
    }
}

// ===========================================================================
// Flash attention, fp16 operands, corrections at fp16-accum rate
// ===========================================================================
#define ASTRIDE   144
#define A_QH      0
#define A_QL      18432
#define A_KV      36864
#define A_KVBUF   36864
#define A_PK      9216
#define A_MS      110592
#define ATTN_SMEM 110720

__global__ __launch_bounds__(256, 1) void attn_tc(
    const __half* __restrict__ qkvh, const __half* __restrict__ qkvl,
    const unsigned char* __restrict__ seq_mask,
    __half* __restrict__ oh, __half* __restrict__ ol)
{
    extern __shared__ char smem[];
    const uint32_t sb = smem_u32(smem);
    const int qt = blockIdx.x, h = blockIdx.y, b = blockIdx.z;
    const int tid = threadIdx.x, warp = tid >> 5, lane = tid & 31;
    const int q0 = qt * 128;
    const int hoff = h * HDIM;

    #pragma unroll
    for (int p = 0; p < 8; p++) {
        const __half* s = (p < 4) ? qkvh : qkvl;
        int idx = (p & 3) * 256 + tid;
        int row = idx >> 3, c = idx & 7;
        size_t src = (size_t)(b * SEQ + q0 + row) * QKVS + hoff + c * 8;
        CPA16(sb + (uint32_t)(p >> 2) * 18432 + row * ASTRIDE + c * 16, s + src);
    }
    CP_COMMIT();

    const int nkt = 2 * qt + 2;

#define LOAD_KV(kt_, buf_)                                                     \
    do {                                                                       \
        const int _k0 = (kt_) * 64;                                            \
        const uint32_t bb = sb + A_KV + (uint32_t)(buf_) * A_KVBUF;            \
        _Pragma("unroll")                                                      \
        for (int p = 0; p < 8; p++) {                                          \
            const __half* s = ((p & 2) == 0) ? qkvh : qkvl;                    \
            const int colo = (p < 4) ? DIM : 2 * DIM;                          \
            int idx = (p & 1) * 256 + tid;                                     \
            int row = idx >> 3, c = idx & 7;                                   \
            size_t src = (size_t)(b * SEQ + _k0 + row) * QKVS + colo + hoff + c * 8; \
            const int plane = (p < 2) ? 0 : (p < 4) ? 1 : (p < 6) ? 2 : 3;     \
            CPA16(bb + (uint32_t)plane * A_PK + row * ASTRIDE + c * 16,        \
                  s + src);                                                    \
        }                                                                      \
        if (tid < 16)                                                          \
            CPA4(sb + A_MS + (uint32_t)(buf_) * 64 + tid * 4,                  \
                 seq_mask + b * SEQ + _k0 + tid * 4);                          \
    } while (0)

    LOAD_KV(0, 0);
    CP_COMMIT();
    cp_wait<1>();
    __syncthreads();

    uint32_t qfh[4][4], qfl[4][4];
    {
        uint32_t abase = sb + (warp * 16 + (lane & 15)) * ASTRIDE + (lane >> 4) * 16;
        #pragma unroll
        for (int k16 = 0; k16 < 4; k16++) {
            LDSM4(qfh[k16][0], qfh[k16][1], qfh[k16][2], qfh[k16][3],
                  abase + A_QH + k16 * 32);
            LDSM4(qfl[k16][0], qfl[k16][1], qfl[k16][2], qfl[k16][3],
                  abase + A_QL + k16 * 32);
        }
    }

    float acco[8][4];
    #pragma unroll
    for (int j = 0; j < 8; j++)
        #pragma unroll
        for (int t = 0; t < 4; t++) acco[j][t] = 0.f;
    float m_lo = -1e30f, m_hi = -1e30f, l_lo = 0.f, l_hi = 0.f;

    const int qrow_lo = q0 + warp * 16 + (lane >> 2);
    const int qrow_hi = qrow_lo + 8;

    for (int kt = 0; kt < nkt; kt++) {
        cp_wait<0>();
        __syncthreads();
        if (kt + 1 < nkt) {
            LOAD_KV(kt + 1, (kt + 1) & 1);
            CP_COMMIT();
        }

        const int k0 = kt * 64;
        const uint32_t bufb = sb + A_KV + (uint32_t)(kt & 1) * A_KVBUF;
        const bool active = (k0 <= q0 + warp * 16 + 15);

        if (active) {
            float accs[8][4];
            uint32_t crr[8][2];
            #pragma unroll
            for (int j = 0; j < 8; j++) {
                #pragma unroll
                for (int t = 0; t < 4; t++) accs[j][t] = 0.f;
                crr[j][0] = 0u; crr[j][1] = 0u;
            }

            #pragma unroll
            for (int k16 = 0; k16 < 4; k16++) {
                #pragma unroll
                for (int g = 0; g < 4; g++) {
                    uint32_t kh4[4], kl4[4];
                    uint32_t bd = bufb + (g * 16 + ((lane >> 4) & 1) * 8 + (lane & 7)) * ASTRIDE
                                + ((lane >> 3) & 1) * 16 + k16 * 32;
                    LDSM4(kh4[0], kh4[1], kh4[2], kh4[3], bd);
                    LDSM4(kl4[0], kl4[1], kl4[2], kl4[3], bd + A_PK);
                    const int j0 = g * 2;
                    MMAF(accs[j0],   qfh[k16][0], qfh[k16][1], qfh[k16][2], qfh[k16][3], kh4[0], kh4[1]);
                    MMAC(crr[j0],    qfh[k16][0], qfh[k16][1], qfh[k16][2], qfh[k16][3], kl4[0], kl4[1]);
                    MMAC(crr[j0],    qfl[k16][0], qfl[k16][1], qfl[k16][2], qfl[k16][3], kh4[0], kh4[1]);
                    MMAF(accs[j0+1], qfh[k16][0], qfh[k16][1], qfh[k16][2], qfh[k16][3], kh4[2], kh4[3]);
                    MMAC(crr[j0+1],  qfh[k16][0], qfh[k16][1], qfh[k16][2], qfh[k16][3], kl4[2], kl4[3]);
                    MMAC(crr[j0+1],  qfl[k16][0], qfl[k16][1], qfl[k16][2], qfl[k16][3], kh4[2], kh4[3]);
                }
            }
            #pragma unroll
            for (int j = 0; j < 8; j++) {
                float2 c01 = unpack_h2(crr[j][0]);
                float2 c23 = unpack_h2(crr[j][1]);
                accs[j][0] += c01.x * CSCALE;  accs[j][1] += c01.y * CSCALE;
                accs[j][2] += c23.x * CSCALE;  accs[j][3] += c23.y * CSCALE;
            }

            const unsigned char* msk = (const unsigned char*)smem + A_MS + (kt & 1) * 64;
            const bool causal = (k0 + 63 > q0 + warp * 16);
            float rmax_lo = -1e30f, rmax_hi = -1e30f;
            #pragma unroll
            for (int j = 0; j < 8; j++) {
                int kloc = j * 8 + 2 * (lane & 3);
                int key0 = k0 + kloc;
                bool sm0 = msk[kloc] != 0, sm1 = msk[kloc + 1] != 0;
                float s0 = accs[j][0] * ATTN_SCALE, s1 = accs[j][1] * ATTN_SCALE;
                float s2 = accs[j][2] * ATTN_SCALE, s3 = accs[j][3] * ATTN_SCALE;
                if (sm0 || (causal && key0     > qrow_lo)) s0 = -10000.0f;
                if (sm1 || (causal && key0 + 1 > qrow_lo)) s1 = -10000.0f;
                if (sm0 || (causal && key0     > qrow_hi)) s2 = -10000.0f;
                if (sm1 || (causal && key0 + 1 > qrow_hi)) s3 = -10000.0f;
                accs[j][0] = s0; accs[j][1] = s1; accs[j][2] = s2; accs[j][3] = s3;
                rmax_lo = fmaxf(rmax_lo, fmaxf(s0, s1));
                rmax_hi = fmaxf(rmax_hi, fmaxf(s2, s3));
            }
            rmax_lo = fmaxf(rmax_lo, __shfl_xor_sync(0xffffffffu, rmax_lo, 1));
            rmax_lo = fmaxf(rmax_lo, __shfl_xor_sync(0xffffffffu, rmax_lo, 2));
            rmax_hi = fmaxf(rmax_hi, __shfl_xor_sync(0xffffffffu, rmax_hi, 1));
            rmax_hi = fmaxf(rmax_hi, __shfl_xor_sync(0xffffffffu, rmax_hi, 2));

            float mnew_lo = fmaxf(m_lo, rmax_lo), mnew_hi = fmaxf(m_hi, rmax_hi);
            float corr_lo = __expf(m_lo - mnew_lo), corr_hi = __expf(m_hi - mnew_hi);
            m_lo = mnew_lo; m_hi = mnew_hi;

            float sum_lo = 0.f, sum_hi = 0.f;
            #pragma unroll
            for (int j = 0; j < 8; j++) {
                float p0 = __expf(accs[j][0] - mnew_lo);
                float p1 = __expf(accs[j][1] - mnew_lo);
                float p2 = __expf(accs[j][2] - mnew_hi);
                float p3 = __expf(accs[j][3] - mnew_hi);
                accs[j][0] = p0; accs[j][1] = p1; accs[j][2] = p2; accs[j][3] = p3;
                sum_lo += p0 + p1;  sum_hi += p2 + p3;
            }
            sum_lo += __shfl_xor_sync(0xffffffffu, sum_lo, 1);
            sum_lo += __shfl_xor_sync(0xffffffffu, sum_lo, 2);
            sum_hi += __shfl_xor_sync(0xffffffffu, sum_hi, 1);
            sum_hi += __shfl_xor_sync(0xffffffffu, sum_hi, 2);
            l_lo = l_lo * corr_lo + sum_lo;
            l_hi = l_hi * corr_hi + sum_hi;
            #pragma unroll
            for (int j = 0; j < 8; j++) {
                acco[j][0] *= corr_lo; acco[j][1] *= corr_lo;
                acco[j][2] *= corr_hi; acco[j][3] *= corr_hi;
            }

            // P -> fp16 hi/lo fragments (lo scaled by 2048)
            uint32_t pfh[4][4], pfl[4][4];
            #pragma unroll
            for (int kk = 0; kk < 4; kk++) {
                const int j0 = kk * 2, j1 = kk * 2 + 1;
                float pv[8] = { accs[j0][0], accs[j0][1], accs[j0][2], accs[j0][3],
                                accs[j1][0], accs[j1][1], accs[j1][2], accs[j1][3] };
                #pragma unroll
                for (int r = 0; r < 4; r++) {
                    __half2 hh = __floats2half2_rn(pv[r*2], pv[r*2+1]);
                    pfh[kk][r] = *reinterpret_cast<uint32_t*>(&hh);
                    __half2 ll = __floats2half2_rn((pv[r*2]   - __low2float(hh))  * LSCALE,
                                                   (pv[r*2+1] - __high2float(hh)) * LSCALE);
                    pfl[kk][r] = *reinterpret_cast<uint32_t*>(&ll);
                }
            }

            #pragma unroll
            for (int j = 0; j < 8; j++) { crr[j][0] = 0u; crr[j][1] = 0u; }
            #pragma unroll
            for (int kk = 0; kk < 4; kk++) {
                #pragma unroll
                for (int g = 0; g < 4; g++) {
                    uint32_t vh4[4], vl4[4];
                    uint32_t vd = bufb + 2 * A_PK
                                + (kk * 16 + (lane & 7) + ((lane >> 3) & 1) * 8) * ASTRIDE
                                + g * 32 + ((lane >> 4) & 1) * 16;
                    LDSM4T(vh4[0], vh4[1], vh4[2], vh4[3], vd);
                    LDSM4T(vl4[0], vl4[1], vl4[2], vl4[3], vd + A_PK);
                    const int j0 = g * 2;
                    MMAF(acco[j0],   pfh[kk][0], pfh[kk][1], pfh[kk][2], pfh[kk][3], vh4[0], vh4[1]);
                    MMAC(crr[j0],    pfh[kk][0], pfh[kk][1], pfh[kk][2], pfh[kk][3], vl4[0], vl4[1]);
                    MMAC(crr[j0],    pfl[kk][0], pfl[kk][1], pfl[kk][2], pfl[kk][3], vh4[0], vh4[1]);
                    MMAF(acco[j0+1], pfh[kk][0], pfh[kk][1], pfh[kk][2], pfh[kk][3], vh4[2], vh4[3]);
                    MMAC(crr[j0+1],  pfh[kk][0], pfh[kk][1], pfh[kk][2], pfh[kk][3], vl4[2], vl4[3]);
                    MMAC(crr[j0+1],  pfl[kk][0], pfl[kk][1], pfl[kk][2], pfl[kk][3], vh4[2], vh4[3]);
                }
            }
            #pragma unroll
            for (int j = 0; j < 8; j++) {
                float2 c01 = unpack_h2(crr[j][0]);
                float2 c23 = unpack_h2(crr[j][1]);
                acco[j][0] += c01.x * CSCALE;  acco[j][1] += c01.y * CSCALE;
                acco[j][2] += c23.x * CSCALE;  acco[j][3] += c23.y * CSCALE;
            }
        }
        __syncthreads();
    }
#undef LOAD_KV

    const float inv_lo = 1.0f / l_lo, inv_hi = 1.0f / l_hi;
    const size_t row_lo = (size_t)(b * SEQ) + qrow_lo;
    const size_t row_hi = row_lo + 8;
    #pragma unroll
    for (int j = 0; j < 8; j++) {
        const int col = hoff + j * 8 + (lane & 3) * 2;
        float o0 = acco[j][0] * inv_lo, o1 = acco[j][1] * inv_lo;
        float o2 = acco[j][2] * inv_hi, o3 = acco[j][3] * inv_hi;
        __half2 h0 = __floats2half2_rn(o0, o1);
        __half2 h1 = __floats2half2_rn(o2, o3);
        __half2 l0 = __floats2half2_rn((o0 - __low2float(h0)) * LSCALE,
                                       (o1 - __high2float(h0)) * LSCALE);
        __half2 l1 = __floats2half2_rn((o2 - __low2float(h1)) * LSCALE,
                                       (o3 - __high2float(h1)) * LSCALE);
        *reinterpret_cast<__half2*>(oh + row_lo * DIM + col) = h0;
        *reinterpret_cast<__half2*>(oh + row_hi * DIM + col) = h1;
        *reinterpret_cast<__half2*>(ol + row_lo * DIM + col) = l0;
        *reinterpret_cast<__half2*>(ol + row_hi * DIM + col) = l1;
    }
}

// ===========================================================================
// Launch
// ===========================================================================
extern "C" void kernel_launch(void* const* d_in, const int* in_sizes, int n_in,
                              void* d_out, int out_size)
{
    const float*         x        = (const float*)d_in[0];
    const unsigned char* seq_mask = (const unsigned char*)d_in[1];
    const float*         wq       = (const float*)d_in[2];
    const float*         wk       = (const float*)d_in[3];
    const float*         wv       = (const float*)d_in[4];
    const float*         wo       = (const float*)d_in[5];
    const float*         g1       = (const float*)d_in[6];
    const float*         b1       = (const float*)d_in[7];
    const float*         g2       = (const float*)d_in[8];
    const float*         b2       = (const float*)d_in[9];
    const float*         w_mlp1   = (const float*)d_in[10];
    const float*         b_mlp1   = (const float*)d_in[11];
    const float*         w_mlp2   = (const float*)d_in[12];
    const float*         b_mlp2   = (const float*)d_in[13];
    float*               out      = (float*)d_out;

    float* x1;
    cudaGetSymbolAddress((void**)&x1, g_x1);

    __half *nxh,*nxl,*qkvh,*qkvl,*ath,*atl,*hh,*hl;
    __half *wqkvh,*wqkvl,*woh,*wol,*m1h,*m1l,*m2h,*m2l;
    cudaGetSymbolAddress((void**)&nxh,   g_nx_hi);  cudaGetSymbolAddress((void**)&nxl,   g_nx_lo);
    cudaGetSymbolAddress((void**)&qkvh,  g_qkv_hi); cudaGetSymbolAddress((void**)&qkvl,  g_qkv_lo);
    cudaGetSymbolAddress((void**)&ath,   g_at_hi);  cudaGetSymbolAddress((void**)&atl,   g_at_lo);
    cudaGetSymbolAddress((void**)&hh,    g_h_hi);   cudaGetSymbolAddress((void**)&hl,    g_h_lo);
    cudaGetSymbolAddress((void**)&wqkvh, g_wqkv_hi);cudaGetSymbolAddress((void**)&wqkvl, g_wqkv_lo);
    cudaGetSymbolAddress((void**)&woh,   g_wo_hi);  cudaGetSymbolAddress((void**)&wol,   g_wo_lo);
    cudaGetSymbolAddress((void**)&m1h,   g_m1_hi);  cudaGetSymbolAddress((void**)&m1l,   g_m1_lo);
    cudaGetSymbolAddress((void**)&m2h,   g_m2_hi);  cudaGetSymbolAddress((void**)&m2l,   g_m2_lo);

    cudaFuncSetAttribute(gemm_tc<EPI_RESID>,      cudaFuncAttributeMaxDynamicSharedMemorySize, GEMM_SMEM);
    cudaFuncSetAttribute(gemm_tc<EPI_BIAS_RESID>, cudaFuncAttributeMaxDynamicSharedMemorySize, GEMM_SMEM);
    cudaFuncSetAttribute(gemm_tc<EPI_HILO>,       cudaFuncAttributeMaxDynamicSharedMemorySize, GEMM_SMEM);
    cudaFuncSetAttribute(gemm_tc<EPI_GELU_HILO>,  cudaFuncAttributeMaxDynamicSharedMemorySize, GEMM_SMEM);
    cudaFuncSetAttribute(attn_tc,                 cudaFuncAttributeMaxDynamicSharedMemorySize, ATTN_SMEM);

    dim3 blk(256);

    // 0,1: weight splits (2 launches)
    split_attn_w<<<4096, blk>>>(wq, wk, wv, wo, wqkvh, wqkvl, woh, wol);
    split_mlp_w <<<8192, blk>>>(w_mlp1, w_mlp2, m1h, m1l, m2h, m2l);

    // 2: nx = LN(x)
    ln_hilo_kernel<<<NTOK, blk>>>(x, g1, b1, nxh, nxl);

    // 3: fused qkv projection (N = 3072)
    dim3 gqkv(QKVS / 64, NTOK / 128);    // (48, 32)
    gemm_tc<EPI_HILO><<<gqkv, blk, GEMM_SMEM>>>(nxh, nxl, wqkvh, wqkvl, nullptr, nullptr, nullptr, qkvh, qkvl, NTOK, QKVS, DIM);

    // 4: flash attention
    dim3 gattn(SEQ / 128, NHEAD, BATCH);
    attn_tc<<<gattn, blk, ATTN_SMEM>>>(qkvh, qkvl, seq_mask, ath, atl);

    // 5: x1 = x + attn @ wo^T   (ncu -s 5 profiles this GEMM)
    dim3 gproj(DIM / 64, NTOK / 128);    // (16, 32)
    gemm_tc<EPI_RESID><<<gproj, blk, GEMM_SMEM>>>(ath, atl, woh, wol, nullptr, x, x1, nullptr, nullptr, NTOK, DIM, DIM);

    // 6: nx = LN(x1)
    ln_hilo_kernel<<<NTOK, blk>>>(x1, g2, b2, nxh, nxl);

    // 7: h = gelu(nx @ w_mlp1^T + b_mlp1)
    dim3 gmlp1(HID / 64, NTOK / 128);    // (64, 32)
    gemm_tc<EPI_GELU_HILO><<<gmlp1, blk, GEMM_SMEM>>>(nxh, nxl, m1h, m1l, b_mlp1, nullptr, nullptr, hh, hl, NTOK, HID, DIM);

    // 8: out = x1 + h @ w_mlp2^T + b_mlp2
    dim3 gmlp2(DIM / 64, NTOK / 128);    // (16, 32)
    gemm_tc<EPI_BIAS_RESID><<<gmlp2, blk, GEMM_SMEM>>>(hh, hl, m2h, m2l, b_mlp2, x1, out, nullptr, nullptr, NTOK, DIM, HID);
}

// round 8
// speedup vs baseline: 1.1066x; 1.1066x over previous
#include <cuda_runtime.h>
#include <cuda_bf16.h>
#include <math.h>
#include <stdint.h>

#define DIM   1024
#define BATCH 2
#define SEQ   2048
#define NHEAD 16
#define HDIM  64
#define NTOK  (BATCH * SEQ)
#define HID   (4 * DIM)
#define QKVS  (3 * DIM)
#define ATTN_SCALE 0.125f
#define LN_EPS 1e-5f

// ===========================================================================
// PTX helpers
// ===========================================================================
static __device__ __forceinline__ uint32_t smem_u32(const void* p) {
    uint32_t a;
    asm("{ .reg .u64 t; cvta.to.shared.u64 t, %1; cvt.u32.u64 %0, t; }"
        : "=r"(a) : "l"(p));
    return a;
}

#define LDSM4(r0, r1, r2, r3, addr) \
    asm volatile("ldmatrix.sync.aligned.m8n8.x4.shared.b16 {%0,%1,%2,%3}, [%4];" \
        : "=r"(r0), "=r"(r1), "=r"(r2), "=r"(r3) : "r"(addr))

#define LDSM4T(r0, r1, r2, r3, addr) \
    asm volatile("ldmatrix.sync.aligned.m8n8.x4.trans.shared.b16 {%0,%1,%2,%3}, [%4];" \
        : "=r"(r0), "=r"(r1), "=r"(r2), "=r"(r3) : "r"(addr))

#define MMA16816(d, a0, a1, a2, a3, b0, b1) \
    asm volatile("mma.sync.aligned.m16n8k16.row.col.f32.bf16.bf16.f32 " \
        "{%0,%1,%2,%3}, {%4,%5,%6,%7}, {%8,%9}, {%0,%1,%2,%3};" \
        : "+f"((d)[0]), "+f"((d)[1]), "+f"((d)[2]), "+f"((d)[3]) \
        : "r"(a0), "r"(a1), "r"(a2), "r"(a3), "r"(b0), "r"(b1))

#define CPA16(dst, src) \
    asm volatile("cp.async.cg.shared.global [%0], [%1], 16;" :: "r"(dst), "l"(src))
#define CPA4(dst, src) \
    asm volatile("cp.async.ca.shared.global [%0], [%1], 4;" :: "r"(dst), "l"(src))
#define CP_COMMIT() asm volatile("cp.async.commit_group;")
template<int N> static __device__ __forceinline__ void cp_wait() {
    asm volatile("cp.async.wait_group %0;" :: "n"(N));
}

static __device__ __forceinline__ uint32_t pack_bf16(float a, float b) {
    __nv_bfloat162 t = __floats2bfloat162_rn(a, b);
    return *reinterpret_cast<uint32_t*>(&t);
}

// ===========================================================================
// Scratch
// ===========================================================================
__device__ float g_x1 [NTOK * DIM];

__device__ __nv_bfloat16 g_nx_hi [NTOK * DIM],  g_nx_lo [NTOK * DIM];
__device__ __nv_bfloat16 g_qkv_hi[NTOK * QKVS], g_qkv_lo[NTOK * QKVS];
__device__ __nv_bfloat16 g_at_hi [NTOK * DIM],  g_at_lo [NTOK * DIM];
__device__ __nv_bfloat16 g_h_hi  [NTOK * HID],  g_h_lo  [NTOK * HID];
__device__ __nv_bfloat16 g_wqkv_hi[QKVS * DIM], g_wqkv_lo[QKVS * DIM];
__device__ __nv_bfloat16 g_wo_hi [DIM * DIM],   g_wo_lo [DIM * DIM];
__device__ __nv_bfloat16 g_m1_hi [HID * DIM],   g_m1_lo [HID * DIM];
__device__ __nv_bfloat16 g_m2_hi [DIM * HID],   g_m2_lo [DIM * HID];

// ===========================================================================
// fused fp32 -> bf16 hi/lo weight splits
// ===========================================================================
static __device__ __forceinline__ void split4(
    const float* __restrict__ src, __nv_bfloat16* __restrict__ hi,
    __nv_bfloat16* __restrict__ lo, int i)
{
    float4 v = *reinterpret_cast<const float4*>(src + i);
    __nv_bfloat162 h01 = __floats2bfloat162_rn(v.x, v.y);
    __nv_bfloat162 h23 = __floats2bfloat162_rn(v.z, v.w);
    __nv_bfloat162 l01 = __floats2bfloat162_rn(v.x - __bfloat162float(h01.x),
                                               v.y - __bfloat162float(h01.y));
    __nv_bfloat162 l23 = __floats2bfloat162_rn(v.z - __bfloat162float(h23.x),
                                               v.w - __bfloat162float(h23.y));
    *reinterpret_cast<__nv_bfloat162*>(hi + i)     = h01;
    *reinterpret_cast<__nv_bfloat162*>(hi + i + 2) = h23;
    *reinterpret_cast<__nv_bfloat162*>(lo + i)     = l01;
    *reinterpret_cast<__nv_bfloat162*>(lo + i + 2) = l23;
}

__global__ __launch_bounds__(256) void split_attn_w(
    const float* __restrict__ wq, const float* __restrict__ wk,
    const float* __restrict__ wv, const float* __restrict__ wo,
    __nv_bfloat16* __restrict__ qkvh, __nv_bfloat16* __restrict__ qkvl,
    __nv_bfloat16* __restrict__ woh, __nv_bfloat16* __restrict__ wol)
{
    int sel = blockIdx.x >> 10;
    int i = ((blockIdx.x & 1023) * 256 + threadIdx.x) * 4;
    if      (sel == 0) split4(wq, qkvh,                 qkvl,                 i);
    else if (sel == 1) split4(wk, qkvh + DIM * DIM,     qkvl + DIM * DIM,     i);
    else if (sel == 2) split4(wv, qkvh + 2 * DIM * DIM, qkvl + 2 * DIM * DIM, i);
    else               split4(wo, woh, wol, i);
}

__global__ __launch_bounds__(256) void split_mlp_w(
    const float* __restrict__ m1, const float* __restrict__ m2,
    __nv_bfloat16* __restrict__ m1h, __nv_bfloat16* __restrict__ m1l,
    __nv_bfloat16* __restrict__ m2h, __nv_bfloat16* __restrict__ m2l)
{
    int sel = blockIdx.x >> 12;
    int i = ((blockIdx.x & 4095) * 256 + threadIdx.x) * 4;
    if (sel == 0) split4(m1, m1h, m1l, i);
    else          split4(m2, m2h, m2l, i);
}

// ===========================================================================
// LayerNorm -> bf16 hi/lo
// ===========================================================================
__global__ __launch_bounds__(256) void ln_hilo_kernel(
    const float* __restrict__ x, const float* __restrict__ g,
    const float* __restrict__ b, __nv_bfloat16* __restrict__ yh,
    __nv_bfloat16* __restrict__ yl)
{
    int row = blockIdx.x;
    int tid = threadIdx.x;
    const float4* xr = reinterpret_cast<const float4*>(x + (size_t)row * DIM);
    float4 v = xr[tid];
    float s  = v.x + v.y + v.z + v.w;
    float sq = v.x*v.x + v.y*v.y + v.z*v.z + v.w*v.w;
    #pragma unroll
    for (int o = 16; o > 0; o >>= 1) {
        s  += __shfl_xor_sync(0xffffffffu, s,  o);
        sq += __shfl_xor_sync(0xffffffffu, sq, o);
    }
    __shared__ float rs[8], rq[8];
    int warp = tid >> 5, lane = tid & 31;
    if (lane == 0) { rs[warp] = s; rq[warp] = sq; }
    __syncthreads();
    if (warp == 0) {
        float a = (lane < 8) ? rs[lane] : 0.f;
        float c = (lane < 8) ? rq[lane] : 0.f;
        #pragma unroll
        for (int o = 4; o > 0; o >>= 1) {
            a += __shfl_xor_sync(0xffffffffu, a, o);
            c += __shfl_xor_sync(0xffffffffu, c, o);
        }
        if (lane == 0) { rs[0] = a; rq[0] = c; }
    }
    __syncthreads();
    float mean = rs[0] * (1.0f / DIM);
    float var  = rq[0] * (1.0f / DIM) - mean * mean;
    float inv  = rsqrtf(var + LN_EPS);
    float4 gv = reinterpret_cast<const float4*>(g)[tid];
    float4 bv = reinterpret_cast<const float4*>(b)[tid];
    float o0 = (v.x - mean) * inv * gv.x + bv.x;
    float o1 = (v.y - mean) * inv * gv.y + bv.y;
    float o2 = (v.z - mean) * inv * gv.z + bv.z;
    float o3 = (v.w - mean) * inv * gv.w + bv.w;
    size_t base = (size_t)row * DIM + tid * 4;
    __nv_bfloat162 h01 = __floats2bfloat162_rn(o0, o1);
    __nv_bfloat162 h23 = __floats2bfloat162_rn(o2, o3);
    __nv_bfloat162 l01 = __floats2bfloat162_rn(o0 - __bfloat162float(h01.x),
                                               o1 - __bfloat162float(h01.y));
    __nv_bfloat162 l23 = __floats2bfloat162_rn(o2 - __bfloat162float(h23.x),
                                               o3 - __bfloat162float(h23.y));
    *reinterpret_cast<__nv_bfloat162*>(yh + base)     = h01;
    *reinterpret_cast<__nv_bfloat162*>(yh + base + 2) = h23;
    *reinterpret_cast<__nv_bfloat162*>(yl + base)     = l01;
    *reinterpret_cast<__nv_bfloat162*>(yl + base + 2) = l23;
}

// ===========================================================================
// HMMA bf16 GEMM, hi/lo compensated, occ 2, ILP-ordered MMA passes
// ===========================================================================
#define EPI_RESID      1
#define EPI_BIAS_RESID 3
#define EPI_HILO       4
#define EPI_GELU_HILO  5

__device__ __forceinline__ float gelu_exact(float x) {
    return 0.5f * x * (1.0f + erff(x * 0.70710678118654752f));
}

#define ROWB      80
#define PLANE     (128 * ROWB)
#define OFF_AHI   0
#define OFF_ALO   (PLANE)
#define OFF_BHI   (2 * PLANE)
#define OFF_BLO   (3 * PLANE)
#define BUF_SZ    (4 * PLANE)
#define GEMM_SMEM (2 * BUF_SZ)      // 81920 B -> 2 CTAs/SM

template<int EPI>
__global__ __launch_bounds__(256, 2) void gemm_tc(
    const __nv_bfloat16* __restrict__ Ahi, const __nv_bfloat16* __restrict__ Alo,
    const __nv_bfloat16* __restrict__ Whi, const __nv_bfloat16* __restrict__ Wlo,
    const float* __restrict__ bias, const float* __restrict__ resid,
    float* __restrict__ Y, __nv_bfloat16* __restrict__ Yh,
    __nv_bfloat16* __restrict__ Yl, int M, int N, int K)
{
    extern __shared__ char smem[];
    const uint32_t sb = smem_u32(smem);
    const int tid  = threadIdx.x;
    const int lane = tid & 31;
    const int wid  = tid >> 5;
    const int bm = blockIdx.y * 128;
    const int bn = blockIdx.x * 128;
    const int wm = (wid & 3) * 32;
    const int wn = (wid >> 2) * 64;

    float acc[2][8][4];
    #pragma unroll
    for (int i = 0; i < 2; i++)
        #pragma unroll
        for (int j = 0; j < 8; j++)
            #pragma unroll
            for (int t = 0; t < 4; t++) acc[i][j][t] = 0.f;

    const int g0r = tid >> 2,         g0c = tid & 3;
    const int g1r = (tid + 256) >> 2;

    const uint32_t a_row   = wm + (lane & 15);
    const uint32_t a_cbyte = (lane >> 4) * 16;
    const uint32_t b_row0  = wn + ((lane >> 4) & 1) * 8 + (lane & 7);
    const uint32_t b_cbyte = ((lane >> 3) & 1) * 16;

    const int NC = K >> 5;

#define LOAD_CHUNK(cidx, bufbase)                                              \
    do {                                                                       \
        const int _k0 = (cidx) << 5;                                           \
        {                                                                      \
            size_t s0 = (size_t)(bm + g0r) * K + _k0 + g0c * 8;                \
            size_t s1 = (size_t)(bm + g1r) * K + _k0 + g0c * 8;                \
            uint32_t d0 = (bufbase) + g0r * ROWB + g0c * 16;                   \
            uint32_t d1 = (bufbase) + g1r * ROWB + g0c * 16;                   \
            CPA16(d0 + OFF_AHI, Ahi + s0); CPA16(d1 + OFF_AHI, Ahi + s1);      \
            CPA16(d0 + OFF_ALO, Alo + s0); CPA16(d1 + OFF_ALO, Alo + s1);      \
        }                                                                      \
        {                                                                      \
            size_t s0 = (size_t)(bn + g0r) * K + _k0 + g0c * 8;                \
            size_t s1 = (size_t)(bn + g1r) * K + _k0 + g0c * 8;                \
            uint32_t d0 = (bufbase) + g0r * ROWB + g0c * 16;                   \
            uint32_t d1 = (bufbase) + g1r * ROWB + g0c * 16;                   \
            CPA16(d0 + OFF_BHI, Whi + s0); CPA16(d1 + OFF_BHI, Whi + s1);      \
            CPA16(d0 + OFF_BLO, Wlo + s0); CPA16(d1 + OFF_BLO, Wlo + s1);      \
        }                                                                      \
    } while (0)

    LOAD_CHUNK(0, sb);
    CP_COMMIT();

    for (int c = 0; c < NC; c++) {
        const uint32_t buf = sb + (uint32_t)(c & 1) * BUF_SZ;
        if (c + 1 < NC) {
            LOAD_CHUNK(c + 1, sb + (uint32_t)((c + 1) & 1) * BUF_SZ);
            CP_COMMIT();
            cp_wait<1>();
        } else {
            cp_wait<0>();
        }
        __syncthreads();

        #pragma unroll
        for (int k16 = 0; k16 < 2; k16++) {
            const uint32_t kb = k16 * 32;
            uint32_t ah[2][4], al[2][4], bh[4][4], bl[4][4];
            // --- load all fragments for this k16 ---
            #pragma unroll
            for (int mi = 0; mi < 2; mi++) {
                uint32_t ad = buf + (a_row + mi * 16) * ROWB + kb + a_cbyte;
                LDSM4(ah[mi][0], ah[mi][1], ah[mi][2], ah[mi][3], ad + OFF_AHI);
                LDSM4(al[mi][0], al[mi][1], al[mi][2], al[mi][3], ad + OFF_ALO);
            }
            #pragma unroll
            for (int p = 0; p < 4; p++) {
                uint32_t bd = buf + (b_row0 + p * 16) * ROWB + kb + b_cbyte;
                LDSM4(bh[p][0], bh[p][1], bh[p][2], bh[p][3], bd + OFF_BHI);
                LDSM4(bl[p][0], bl[p][1], bl[p][2], bl[p][3], bd + OFF_BLO);
            }
            // --- pass 1: hi*hi (16 independent MMAs) ---
            #pragma unroll
            for (int mi = 0; mi < 2; mi++)
                #pragma unroll
                for (int j = 0; j < 8; j++) {
                    const int p = j >> 1, q = (j & 1) * 2;
                    MMA16816(acc[mi][j], ah[mi][0], ah[mi][1], ah[mi][2], ah[mi][3],
                             bh[p][q], bh[p][q + 1]);
                }
            // --- pass 2: hi*lo ---
            #pragma unroll
            for (int mi = 0; mi < 2; mi++)
                #pragma unroll
                for (int j = 0; j < 8; j++) {
                    const int p = j >> 1, q = (j & 1) * 2;
                    MMA16816(acc[mi][j], ah[mi][0], ah[mi][1], ah[mi][2], ah[mi][3],
                             bl[p][q], bl[p][q + 1]);
                }
            // --- pass 3: lo*hi ---
            #pragma unroll
            for (int mi = 0; mi < 2; mi++)
                #pragma unroll
                for (int j = 0; j < 8; j++) {
                    const int p = j >> 1, q = (j & 1) * 2;
                    MMA16816(acc[mi][j], al[mi][0], al[mi][1], al[mi][2], al[mi][3],
                             bh[p][q], bh[p][q + 1]);
                }
        }
        __syncthreads();
    }
#undef LOAD_CHUNK

    #pragma unroll
    for (int mi = 0; mi < 2; mi++) {
        const int r0 = bm + wm + mi * 16 + (lane >> 2);
        #pragma unroll
        for (int j = 0; j < 8; j++) {
            const int col = bn + wn + j * 8 + (lane & 3) * 2;
            float2 v0 = make_float2(acc[mi][j][0], acc[mi][j][1]);
            float2 v1 = make_float2(acc[mi][j][2], acc[mi][j][3]);
            if (EPI == EPI_GELU_HILO) {
                float2 bb = *reinterpret_cast<const float2*>(bias + col);
                v0.x = gelu_exact(v0.x + bb.x);  v0.y = gelu_exact(v0.y + bb.y);
                v1.x = gelu_exact(v1.x + bb.x);  v1.y = gelu_exact(v1.y + bb.y);
            } else if (EPI == EPI_BIAS_RESID) {
                float2 bb = *reinterpret_cast<const float2*>(bias + col);
                float2 r0v = *reinterpret_cast<const float2*>(resid + (size_t)r0 * N + col);
                float2 r1v = *reinterpret_cast<const float2*>(resid + (size_t)(r0 + 8) * N + col);
                v0.x += bb.x + r0v.x;  v0.y += bb.y + r0v.y;
                v1.x += bb.x + r1v.x;  v1.y += bb.y + r1v.y;
            } else if (EPI == EPI_RESID) {
                float2 r0v = *reinterpret_cast<const float2*>(resid + (size_t)r0 * N + col);
                float2 r1v = *reinterpret_cast<const float2*>(resid + (size_t)(r0 + 8) * N + col);
                v0.x += r0v.x;  v0.y += r0v.y;
                v1.x += r1v.x;  v1.y += r1v.y;
            }
            if (EPI == EPI_HILO || EPI == EPI_GELU_HILO) {
                __nv_bfloat162 h0 = __floats2bfloat162_rn(v0.x, v0.y);
                __nv_bfloat162 h1 = __floats2bfloat162_rn(v1.x, v1.y);
                __nv_bfloat162 l0 = __floats2bfloat162_rn(v0.x - __bfloat162float(h0.x),
                                                          v0.y - __bfloat162float(h0.y));
                __nv_bfloat162 l1 = __floats2bfloat162_rn(v1.x - __bfloat162float(h1.x),
                                                          v1.y - __bfloat162float(h1.y));
                *reinterpret_cast<__nv_bfloat162*>(Yh + (size_t)r0 * N + col)       = h0;
                *reinterpret_cast<__nv_bfloat162*>(Yh + (size_t)(r0 + 8) * N + col) = h1;
                *reinterpret_cast<__nv_bfloat162*>(Yl + (size_t)r0 * N + col)       = l0;
                *reinterpret_cast<__nv_bfloat162*>(Yl + (size_t)(r0 + 8) * N + col) = l1;
            } else {
                *reinterpret_cast<float2*>(Y + (size_t)r0 * N + col)       = v0;
                *reinterpret_cast<float2*>(Y + (size_t)(r0 + 8) * N + col) = v1;
            }
        }
    }
}

// ===========================================================================
// Flash attention on HMMA (bf16, 3-term), fused qkv input
// ===========================================================================
#define ASTRIDE   144
#define A_QH      0
#define A_QL      18432
#define A_KV      36864
#define A_KVBUF   36864
#define A_PK      9216
#define A_MS      110592
#define ATTN_SMEM 110720

__global__ __launch_bounds__(256, 1) void attn_tc(
    const __nv_bfloat16* __restrict__ qkvh, const __nv_bfloat16* __restrict__ qkvl,
    const unsigned char* __restrict__ seq_mask,
    __nv_bfloat16* __restrict__ oh, __nv_bfloat16* __restrict__ ol)
{
    extern __shared__ char smem[];
    const uint32_t sb = smem_u32(smem);
    const int qt = blockIdx.x, h = blockIdx.y, b = blockIdx.z;
    const int tid = threadIdx.x, warp = tid >> 5, lane = tid & 31;
    const int q0 = qt * 128;
    const int hoff = h * HDIM;

    #pragma unroll
    for (int p = 0; p < 8; p++) {
        const __nv_bfloat16* s = (p < 4) ? qkvh : qkvl;
        int idx = (p & 3) * 256 + tid;
        int row = idx >> 3, c = idx & 7;
        size_t src = (size_t)(b * SEQ + q0 + row) * QKVS + hoff + c * 8;
        CPA16(sb + (uint32_t)(p >> 2) * 18432 + row * ASTRIDE + c * 16, s + src);
    }
    CP_COMMIT();

    const int nkt = 2 * qt + 2;

#define LOAD_KV(kt_, buf_)                                                     \
    do {                                                                       \
        const int _k0 = (kt_) * 64;                                            \
        const uint32_t bb = sb + A_KV + (uint32_t)(buf_) * A_KVBUF;            \
        _Pragma("unroll")                                                      \
        for (int p = 0; p < 8; p++) {                                          \
            const __nv_bfloat16* s = ((p & 2) == 0) ? qkvh : qkvl;             \
            const int colo = (p < 4) ? DIM : 2 * DIM;                          \
            int idx = (p & 1) * 256 + tid;                                     \
            int row = idx >> 3, c = idx & 7;                                   \
            size_t src = (size_t)(b * SEQ + _k0 + row) * QKVS + colo + hoff + c * 8; \
            const int plane = (p < 2) ? 0 : (p < 4) ? 1 : (p < 6) ? 2 : 3;     \
            CPA16(bb + (uint32_t)plane * A_PK + row * ASTRIDE + c * 16,        \
                  s + src);                                                    \
        }                                                                      \
        if (tid < 16)                                                          \
            CPA4(sb + A_MS + (uint32_t)(buf_) * 64 + tid * 4,                  \
                 seq_mask + b * SEQ + _k0 + tid * 4);                          \
    } while (0)

    LOAD_KV(0, 0);
    CP_COMMIT();
    cp_wait<1>();
    __syncthreads();

    uint32_t qfh[4][4], qfl[4][4];
    {
        uint32_t abase = sb + (warp * 16 + (lane & 15)) * ASTRIDE + (lane >> 4) * 16;
        #pragma unroll
        for (int k16 = 0; k16 < 4; k16++) {
            LDSM4(qfh[k16][0], qfh[k16][1], qfh[k16][2], qfh[k16][3],
                  abase + A_QH + k16 * 32);
            LDSM4(qfl[k16][0], qfl[k16][1], qfl[k16][2], qfl[k16][3],
                  abase + A_QL + k16 * 32);
        }
    }

    float acco[8][4];
    #pragma unroll
    for (int j = 0; j < 8; j++)
        #pragma unroll
        for (int t = 0; t < 4; t++) acco[j][t] = 0.f;
    float m_lo = -1e30f, m_hi = -1e30f, l_lo = 0.f, l_hi = 0.f;

    const int qrow_lo = q0 + warp * 16 + (lane >> 2);
    const int qrow_hi = qrow_lo + 8;

    for (int kt = 0; kt < nkt; kt++) {
        cp_wait<0>();
        __syncthreads();
        if (kt + 1 < nkt) {
            LOAD_KV(kt + 1, (kt + 1) & 1);
            CP_COMMIT();
        }

        const int k0 = kt * 64;
        const uint32_t bufb = sb + A_KV + (uint32_t)(kt & 1) * A_KVBUF;
        const bool active = (k0 <= q0 + warp * 16 + 15);

        if (active) {
            float accs[8][4];
            #pragma unroll
            for (int j = 0; j < 8; j++)
                #pragma unroll
                for (int t = 0; t < 4; t++) accs[j][t] = 0.f;

            #pragma unroll
            for (int k16 = 0; k16 < 4; k16++) {
                #pragma unroll
                for (int g = 0; g < 4; g++) {
                    uint32_t kh4[4], kl4[4];
                    uint32_t bd = bufb + (g * 16 + ((lane >> 4) & 1) * 8 + (lane & 7)) * ASTRIDE
                                + ((lane >> 3) & 1) * 16 + k16 * 32;
                    LDSM4(kh4[0], kh4[1], kh4[2], kh4[3], bd);
                    LDSM4(kl4[0], kl4[1], kl4[2], kl4[3], bd + A_PK);
                    const int j0 = g * 2;
                    MMA16816(accs[j0],   qfh[k16][0], qfh[k16][1], qfh[k16][2], qfh[k16][3], kh4[0], kh4[1]);
                    MMA16816(accs[j0+1], qfh[k16][0], qfh[k16][1], qfh[k16][2], qfh[k16][3], kh4[2], kh4[3]);
                    MMA16816(accs[j0],   qfh[k16][0], qfh[k16][1], qfh[k16][2], qfh[k16][3], kl4[0], kl4[1]);
                    MMA16816(accs[j0+1], qfh[k16][0], qfh[k16][1], qfh[k16][2], qfh[k16][3], kl4[2], kl4[3]);
                    MMA16816(accs[j0],   qfl[k16][0], qfl[k16][1], qfl[k16][2], qfl[k16][3], kh4[0], kh4[1]);
                    MMA16816(accs[j0+1], qfl[k16][0], qfl[k16][1], qfl[k16][2], qfl[k16][3], kh4[2], kh4[3]);
                }
            }

            const unsigned char* msk = (const unsigned char*)smem + A_MS + (kt & 1) * 64;
            const bool causal = (k0 + 63 > q0 + warp * 16);
            float rmax_lo = -1e30f, rmax_hi = -1e30f;
            #pragma unroll
            for (int j = 0; j < 8; j++) {
                int kloc = j * 8 + 2 * (lane & 3);
                int key0 = k0 + kloc;
                bool sm0 = msk[kloc] != 0, sm1 = msk[kloc + 1] != 0;
                float s0 = accs[j][0] * ATTN_SCALE, s1 = accs[j][1] * ATTN_SCALE;
                float s2 = accs[j][2] * ATTN_SCALE, s3 = accs[j][3] * ATTN_SCALE;
                if (sm0 || (causal && key0     > qrow_lo)) s0 = -10000.0f;
                if (sm1 || (causal && key0 + 1 > qrow_lo)) s1 = -10000.0f;
                if (sm0 || (causal && key0     > qrow_hi)) s2 = -10000.0f;
                if (sm1 || (causal && key0 + 1 > qrow_hi)) s3 = -10000.0f;
                accs[j][0] = s0; accs[j][1] = s1; accs[j][2] = s2; accs[j][3] = s3;
                rmax_lo = fmaxf(rmax_lo, fmaxf(s0, s1));
                rmax_hi = fmaxf(rmax_hi, fmaxf(s2, s3));
            }
            rmax_lo = fmaxf(rmax_lo, __shfl_xor_sync(0xffffffffu, rmax_lo, 1));
            rmax_lo = fmaxf(rmax_lo, __shfl_xor_sync(0xffffffffu, rmax_lo, 2));
            rmax_hi = fmaxf(rmax_hi, __shfl_xor_sync(0xffffffffu, rmax_hi, 1));
            rmax_hi = fmaxf(rmax_hi, __shfl_xor_sync(0xffffffffu, rmax_hi, 2));

            float mnew_lo = fmaxf(m_lo, rmax_lo), mnew_hi = fmaxf(m_hi, rmax_hi);
            float corr_lo = __expf(m_lo - mnew_lo), corr_hi = __expf(m_hi - mnew_hi);
            m_lo = mnew_lo; m_hi = mnew_hi;

            float sum_lo = 0.f, sum_hi = 0.f;
            #pragma unroll
            for (int j = 0; j < 8; j++) {
                float p0 = __expf(accs[j][0] - mnew_lo);
                float p1 = __expf(accs[j][1] - mnew_lo);
                float p2 = __expf(accs[j][2] - mnew_hi);
                float p3 = __expf(accs[j][3] - mnew_hi);
                accs[j][0] = p0; accs[j][1] = p1; accs[j][2] = p2; accs[j][3] = p3;
                sum_lo += p0 + p1;  sum_hi += p2 + p3;
            }
            sum_lo += __shfl_xor_sync(0xffffffffu, sum_lo, 1);
            sum_lo += __shfl_xor_sync(0xffffffffu, sum_lo, 2);
            sum_hi += __shfl_xor_sync(0xffffffffu, sum_hi, 1);
            sum_hi += __shfl_xor_sync(0xffffffffu, sum_hi, 2);
            l_lo = l_lo * corr_lo + sum_lo;
            l_hi = l_hi * corr_hi + sum_hi;
            #pragma unroll
            for (int j = 0; j < 8; j++) {
                acco[j][0] *= corr_lo; acco[j][1] *= corr_lo;
                acco[j][2] *= corr_hi; acco[j][3] *= corr_hi;
            }

            uint32_t pfh[4][4], pfl[4][4];
            #pragma unroll
            for (int kk = 0; kk < 4; kk++) {
                const int j0 = kk * 2, j1 = kk * 2 + 1;
                pfh[kk][0] = pack_bf16(accs[j0][0], accs[j0][1]);
                pfh[kk][1] = pack_bf16(accs[j0][2], accs[j0][3]);
                pfh[kk][2] = pack_bf16(accs[j1][0], accs[j1][1]);
                pfh[kk][3] = pack_bf16(accs[j1][2], accs[j1][3]);
                __nv_bfloat162 h0 = *reinterpret_cast<__nv_bfloat162*>(&pfh[kk][0]);
                __nv_bfloat162 h1 = *reinterpret_cast<__nv_bfloat162*>(&pfh[kk][1]);
                __nv_bfloat162 h2 = *reinterpret_cast<__nv_bfloat162*>(&pfh[kk][2]);
                __nv_bfloat162 h3 = *reinterpret_cast<__nv_bfloat162*>(&pfh[kk][3]);
                pfl[kk][0] = pack_bf16(accs[j0][0] - __bfloat162float(h0.x),
                                       accs[j0][1] - __bfloat162float(h0.y));
                pfl[kk][1] = pack_bf16(accs[j0][2] - __bfloat162float(h1.x),
                                       accs[j0][3] - __bfloat162float(h1.y));
                pfl[kk][2] = pack_bf16(accs[j1][0] - __bfloat162float(h2.x),
                                       accs[j1][1] - __bfloat162float(h2.y));
                pfl[kk][3] = pack_bf16(accs[j1][2] - __bfloat162float(h3.x),
                                       accs[j1][3] - __bfloat162float(h3.y));
            }

            #pragma unroll
            for (int kk = 0; kk < 4; kk++) {
                #pragma unroll
                for (int g = 0; g < 4; g++) {
                    uint32_t vh4[4], vl4[4];
                    uint32_t vd = bufb + 2 * A_PK
                                + (kk * 16 + (lane & 7) + ((lane >> 3) & 1) * 8) * ASTRIDE
                                + g * 32 + ((lane >> 4) & 1) * 16;
                    LDSM4T(vh4[0], vh4[1], vh4[2], vh4[3], vd);
                    LDSM4T(vl4[0], vl4[1], vl4[2], vl4[3], vd + A_PK);
                    const int j0 = g * 2;
                    MMA16816(acco[j0],   pfh[kk][0], pfh[kk][1], pfh[kk][2], pfh[kk][3], vh4[0], vh4[1]);
                    MMA16816(acco[j0+1], pfh[kk][0], pfh[kk][1], pfh[kk][2], pfh[kk][3], vh4[2], vh4[3]);
                    MMA16816(acco[j0],   pfl[kk][0], pfl[kk][1], pfl[kk][2], pfl[kk][3], vh4[0], vh4[1]);
                    MMA16816(acco[j0+1], pfl[kk][0], pfl[kk][1], pfl[kk][2], pfl[kk][3], vh4[2], vh4[3]);
                    MMA16816(acco[j0],   pfh[kk][0], pfh[kk][1], pfh[kk][2], pfh[kk][3], vl4[0], vl4[1]);
                    MMA16816(acco[j0+1], pfh[kk][0], pfh[kk][1], pfh[kk][2], pfh[kk][3], vl4[2], vl4[3]);
                }
            }
        }
        __syncthreads();
    }
#undef LOAD_KV

    const float inv_lo = 1.0f / l_lo, inv_hi = 1.0f / l_hi;
    const size_t row_lo = (size_t)(b * SEQ) + qrow_lo;
    const size_t row_hi = row_lo + 8;
    #pragma unroll
    for (int j = 0; j < 8; j++) {
        const int col = hoff + j * 8 + (lane & 3) * 2;
        float o0 = acco[j][0] * inv_lo, o1 = acco[j][1] * inv_lo;
        float o2 = acco[j][2] * inv_hi, o3 = acco[j][3] * inv_hi;
        __nv_bfloat162 h0 = __floats2bfloat162_rn(o0, o1);
        __nv_bfloat162 h1 = __floats2bfloat162_rn(o2, o3);
        __nv_bfloat162 l0 = __floats2bfloat162_rn(o0 - __bfloat162float(h0.x),
                                                  o1 - __bfloat162float(h0.y));
        __nv_bfloat162 l1 = __floats2bfloat162_rn(o2 - __bfloat162float(h1.x),
                                                  o3 - __bfloat162float(h1.y));
        *reinterpret_cast<__nv_bfloat162*>(oh + row_lo * DIM + col) = h0;
        *reinterpret_cast<__nv_bfloat162*>(oh + row_hi * DIM + col) = h1;
        *reinterpret_cast<__nv_bfloat162*>(ol + row_lo * DIM + col) = l0;
        *reinterpret_cast<__nv_bfloat162*>(ol + row_hi * DIM + col) = l1;
    }
}

// ===========================================================================
// Launch
// ===========================================================================
extern "C" void kernel_launch(void* const* d_in, const int* in_sizes, int n_in,
                              void* d_out, int out_size)
{
    const float*         x        = (const float*)d_in[0];
    const unsigned char* seq_mask = (const unsigned char*)d_in[1];
    const float*         wq       = (const float*)d_in[2];
    const float*         wk       = (const float*)d_in[3];
    const float*         wv       = (const float*)d_in[4];
    const float*         wo       = (const float*)d_in[5];
    const float*         g1       = (const float*)d_in[6];
    const float*         b1       = (const float*)d_in[7];
    const float*         g2       = (const float*)d_in[8];
    const float*         b2       = (const float*)d_in[9];
    const float*         w_mlp1   = (const float*)d_in[10];
    const float*         b_mlp1   = (const float*)d_in[11];
    const float*         w_mlp2   = (const float*)d_in[12];
    const float*         b_mlp2   = (const float*)d_in[13];
    float*               out      = (float*)d_out;

    float* x1;
    cudaGetSymbolAddress((void**)&x1, g_x1);

    __nv_bfloat16 *nxh,*nxl,*qkvh,*qkvl,*ath,*atl,*hh,*hl;
    __nv_bfloat16 *wqkvh,*wqkvl,*woh,*wol,*m1h,*m1l,*m2h,*m2l;
    cudaGetSymbolAddress((void**)&nxh,   g_nx_hi);  cudaGetSymbolAddress((void**)&nxl,   g_nx_lo);
    cudaGetSymbolAddress((void**)&qkvh,  g_qkv_hi); cudaGetSymbolAddress((void**)&qkvl,  g_qkv_lo);
    cudaGetSymbolAddress((void**)&ath,   g_at_hi);  cudaGetSymbolAddress((void**)&atl,   g_at_lo);
    cudaGetSymbolAddress((void**)&hh,    g_h_hi);   cudaGetSymbolAddress((void**)&hl,    g_h_lo);
    cudaGetSymbolAddress((void**)&wqkvh, g_wqkv_hi);cudaGetSymbolAddress((void**)&wqkvl, g_wqkv_lo);
    cudaGetSymbolAddress((void**)&woh,   g_wo_hi);  cudaGetSymbolAddress((void**)&wol,   g_wo_lo);
    cudaGetSymbolAddress((void**)&m1h,   g_m1_hi);  cudaGetSymbolAddress((void**)&m1l,   g_m1_lo);
    cudaGetSymbolAddress((void**)&m2h,   g_m2_hi);  cudaGetSymbolAddress((void**)&m2l,   g_m2_lo);

    cudaFuncSetAttribute(gemm_tc<EPI_RESID>,      cudaFuncAttributeMaxDynamicSharedMemorySize, GEMM_SMEM);
    cudaFuncSetAttribute(gemm_tc<EPI_BIAS_RESID>, cudaFuncAttributeMaxDynamicSharedMemorySize, GEMM_SMEM);
    cudaFuncSetAttribute(gemm_tc<EPI_HILO>,       cudaFuncAttributeMaxDynamicSharedMemorySize, GEMM_SMEM);
    cudaFuncSetAttribute(gemm_tc<EPI_GELU_HILO>,  cudaFuncAttributeMaxDynamicSharedMemorySize, GEMM_SMEM);
    cudaFuncSetAttribute(attn_tc,                 cudaFuncAttributeMaxDynamicSharedMemorySize, ATTN_SMEM);

    dim3 blk(256);

    split_attn_w<<<4096, blk>>>(wq, wk, wv, wo, wqkvh, wqkvl, woh, wol);
    split_mlp_w <<<8192, blk>>>(w_mlp1, w_mlp2, m1h, m1l, m2h, m2l);

    ln_hilo_kernel<<<NTOK, blk>>>(x, g1, b1, nxh, nxl);

    dim3 gqkv(QKVS / 128, NTOK / 128);   // (24, 32)
    gemm_tc<EPI_HILO><<<gqkv, blk, GEMM_SMEM>>>(nxh, nxl, wqkvh, wqkvl, nullptr, nullptr, nullptr, qkvh, qkvl, NTOK, QKVS, DIM);

    dim3 gattn(SEQ / 128, NHEAD, BATCH);
    attn_tc<<<gattn, blk, ATTN_SMEM>>>(qkvh, qkvl, seq_mask, ath, atl);

    dim3 gproj(DIM / 128, NTOK / 128);
    gemm_tc<EPI_RESID><<<gproj, blk, GEMM_SMEM>>>(ath, atl, woh, wol, nullptr, x, x1, nullptr, nullptr, NTOK, DIM, DIM);

    ln_hilo_kernel<<<NTOK, blk>>>(x1, g2, b2, nxh, nxl);

    dim3 gmlp1(HID / 128, NTOK / 128);
    gemm_tc<EPI_GELU_HILO><<<gmlp1, blk, GEMM_SMEM>>>(nxh, nxl, m1h, m1l, b_mlp1, nullptr, nullptr, hh, hl, NTOK, HID, DIM);

    dim3 gmlp2(DIM / 128, NTOK / 128);
    gemm_tc<EPI_BIAS_RESID><<<gmlp2, blk, GEMM_SMEM>>>(hh, hl, m2h, m2l, b_mlp2, x1, out, nullptr, nullptr, NTOK, DIM, HID);
}